// round 12
// baseline (speedup 1.0000x reference)
#include <cuda_runtime.h>
#include <cuda_bf16.h>
#include <math.h>
#include <stdint.h>

// ---------------- problem constants ----------------
#define BB   32
#define TW   40
#define T1   38
#define T2T  36
#define NN   50
#define CIN  2
#define HH   128
#define CO   64
#define EE   800
#define NSL  (BB*T1)        // 1216
#define MCHEB (NSL*NN)      // 60800
#define MT2   (BB*NN*T2T)   // 57600
#define LPAD 68

// ---------------- scratch ----------------
__device__ float g_T0r [(size_t)NSL*NN*HH];
__device__ float g_Tx1r[(size_t)NSL*NN*HH];
__device__ float g_Tx2r[(size_t)NSL*NN*HH];
__device__ float g_Gr  [(size_t)NSL*NN*HH];
__device__ float g_T2  [BB*T2T*NN*CO];
__device__ float g_WchebT[128*384];
__device__ float g_WcatT [192*384];
__device__ double g_bnPart[4][NN][2];
__device__ float g_bnA[NN];
__device__ float g_bnC[NN];
__device__ float g_S[BB*3*3200];
__device__ float g_poolPart[25][128][32];
__device__ float g_pooled[BB*128];

__device__ __forceinline__ float sigm(float x){ return 1.f/(1.f+__expf(-x)); }
__device__ __forceinline__ float tf32r(float x){
    uint32_t r; asm("cvt.rna.tf32.f32 %0, %1;" : "=r"(r) : "f"(x));
    return __uint_as_float(r);
}

// ---------------- PTX helpers ----------------
__device__ __forceinline__ uint32_t smem_u32(const void* p){
    uint32_t a;
    asm("{ .reg .u64 t; cvta.to.shared.u64 t, %1; cvt.u32.u64 %0, t; }" : "=r"(a) : "l"(p));
    return a;
}
__device__ __forceinline__ uint32_t swz128(uint32_t off){ return off ^ ((off >> 3) & 0x70); }
__device__ __forceinline__ void cp16(uint32_t dst, const void* src){
    asm volatile("cp.async.cg.shared.global [%0], [%1], 16;" :: "r"(dst), "l"(src));
}
__device__ __forceinline__ void mma_tf32(float* c, const uint32_t* a, const uint32_t* b){
    asm volatile("mma.sync.aligned.m16n8k8.row.col.f32.tf32.tf32.f32 "
        "{%0,%1,%2,%3}, {%4,%5,%6,%7}, {%8,%9}, {%0,%1,%2,%3};"
        : "+f"(c[0]), "+f"(c[1]), "+f"(c[2]), "+f"(c[3])
        : "r"(a[0]),"r"(a[1]),"r"(a[2]),"r"(a[3]), "r"(b[0]),"r"(b[1]));
}
__device__ __forceinline__ uint32_t swzw(int row, int k){
    return swz128((uint32_t)(row*128 + k*4)) >> 2;
}

// ---------------- K1: temporal gated conv 1 ----------------
__global__ void tconv1_kernel(const float* __restrict__ X,
                              const float* __restrict__ w1, const float* __restrict__ b1,
                              const float* __restrict__ w2, const float* __restrict__ b2,
                              const float* __restrict__ w3, const float* __restrict__ b3)
{
    int s = blockIdx.x;
    int b = s / T1, t = s % T1;
    int h = threadIdx.x;
    float W1[6], W2[6], W3[6];
#pragma unroll
    for (int i = 0; i < 6; i++) {
        W1[i] = w1[i*128 + h]; W2[i] = w2[i*128 + h]; W3[i] = w3[i*128 + h];
    }
    float bb1 = b1[h], bb2 = b2[h], bb3 = b3[h];

    __shared__ float xs[3][NN*CIN];
    for (int i = threadIdx.x; i < 3*NN*CIN; i += 128) {
        int kt = i / (NN*CIN), rem = i % (NN*CIN);
        xs[kt][rem] = X[((size_t)(b*TW + t + kt)*NN)*CIN + rem];
    }
    __syncthreads();

    size_t ob = ((size_t)s*NN)*HH + h;
    for (int n = 0; n < NN; n++) {
        float p = bb1, q = bb2, r = bb3;
#pragma unroll
        for (int kt = 0; kt < 3; kt++)
#pragma unroll
            for (int c = 0; c < 2; c++) {
                float xv = xs[kt][n*2 + c];
                p += xv * W1[kt*2 + c]; q += xv * W2[kt*2 + c]; r += xv * W3[kt*2 + c];
            }
        float v = p * sigm(q) + r;
        v = v > 0.f ? v : 0.f;
        g_T0r[ob + (size_t)n*HH] = tf32r(v);
    }
}

// -------- K3: fused edge-prep + dense Chebyshev propagation via tf32 MMA --------
__global__ __launch_bounds__(256, 3)
void prop_dense_kernel(const int* __restrict__ ei)
{
    extern __shared__ __align__(16) float dyn[];
    float* sA = dyn;                  // 64*68: dense L (rows >= 50 stay 0)
    float* sB = dyn + 64*LPAD;        // 128*68: T0^T, then 2*Tx1^T
    __shared__ int   deg[NN];
    __shared__ float dis[NN];

    int s = blockIdx.x;
    int b = s / T1, t = s % T1;
    int tid = threadIdx.x;
    int wid = tid >> 5, lane = tid & 31;
    int wm = (wid & 3) * 16;
    int wn = (wid >> 2) * 64;

    const int* row = ei + (size_t)(b*TW + t)*(2*EE);
    const int* col = row + EE;
    const float* t0p = g_T0r + (size_t)s*NN*HH;

    for (int i = tid; i < 64*LPAD; i += 256) sA[i] = 0.f;
    if (tid < NN) deg[tid] = 0;
    __syncthreads();

    for (int e = tid; e < EE; e += 256) atomicAdd(&deg[row[e]], 1);
    for (int i = tid; i < NN*HH; i += 256) {
        int c = i >> 7, f = i & 127;
        sB[f*LPAD + c] = t0p[i];
    }
    for (int i = tid; i < 128*(LPAD-NN); i += 256) {
        int f = i / (LPAD-NN), c = NN + i % (LPAD-NN);
        sB[f*LPAD + c] = 0.f;
    }
    __syncthreads();
    if (tid < NN) dis[tid] = deg[tid] > 0 ? rsqrtf((float)deg[tid]) : 0.f;
    __syncthreads();
    for (int e = tid; e < EE; e += 256) {
        int r = row[e], c = col[e];
        atomicAdd(&sA[r*LPAD + c], -dis[r]*dis[c]);
    }
    __syncthreads();
    for (int i = tid; i < NN*64; i += 256) {
        int n = i >> 6, c = i & 63;
        sA[n*LPAD + c] = tf32r(sA[n*LPAD + c]);
    }
    __syncthreads();

    int rl = lane >> 2, cl = (lane & 3)*2;
    int m0r = wm + rl, m1r = wm + rl + 8;

    // ---- phase 1: acc = L @ T0 ----
    {
        float acc[8][4];
#pragma unroll
        for (int nf = 0; nf < 8; nf++)
#pragma unroll
            for (int r = 0; r < 4; r++) acc[nf][r] = 0.f;
#pragma unroll
        for (int k8 = 0; k8 < 8; k8++) {
            int kb = k8*8 + (lane & 3);
            float af[4];
            af[0] = sA[m0r*LPAD + kb];
            af[1] = sA[m1r*LPAD + kb];
            af[2] = sA[m0r*LPAD + kb + 4];
            af[3] = sA[m1r*LPAD + kb + 4];
            const uint32_t* a = (const uint32_t*)af;
#pragma unroll
            for (int nf = 0; nf < 8; nf++) {
                float bf[2];
                int f0 = wn + nf*8 + rl;
                bf[0] = sB[f0*LPAD + kb];
                bf[1] = sB[f0*LPAD + kb + 4];
                mma_tf32(acc[nf], a, (const uint32_t*)bf);
            }
        }
        __syncthreads();
        float* gout = g_Tx1r + (size_t)s*NN*HH;
#pragma unroll
        for (int nf = 0; nf < 8; nf++) {
            int f = wn + nf*8 + cl;
            sB[f*LPAD + m0r]     = 2.f*acc[nf][0];
            sB[(f+1)*LPAD + m0r] = 2.f*acc[nf][1];
            sB[f*LPAD + m1r]     = 2.f*acc[nf][2];
            sB[(f+1)*LPAD + m1r] = 2.f*acc[nf][3];
            if (m0r < NN)
                *(float2*)(gout + (size_t)m0r*HH + f) =
                    make_float2(tf32r(acc[nf][0]), tf32r(acc[nf][1]));
            if (m1r < NN)
                *(float2*)(gout + (size_t)m1r*HH + f) =
                    make_float2(tf32r(acc[nf][2]), tf32r(acc[nf][3]));
        }
    }
    __syncthreads();

    // ---- phase 2: acc = -T0 + L @ (2*Tx1) ----
    {
        float acc[8][4];
#pragma unroll
        for (int nf = 0; nf < 8; nf++) {
            int f = wn + nf*8 + cl;
            if (m0r < NN) {
                float2 v = *(const float2*)(t0p + (size_t)m0r*HH + f);
                acc[nf][0] = -v.x; acc[nf][1] = -v.y;
            } else { acc[nf][0] = 0.f; acc[nf][1] = 0.f; }
            if (m1r < NN) {
                float2 v = *(const float2*)(t0p + (size_t)m1r*HH + f);
                acc[nf][2] = -v.x; acc[nf][3] = -v.y;
            } else { acc[nf][2] = 0.f; acc[nf][3] = 0.f; }
        }
#pragma unroll
        for (int k8 = 0; k8 < 8; k8++) {
            int kb = k8*8 + (lane & 3);
            float af[4];
            af[0] = sA[m0r*LPAD + kb];
            af[1] = sA[m1r*LPAD + kb];
            af[2] = sA[m0r*LPAD + kb + 4];
            af[3] = sA[m1r*LPAD + kb + 4];
            const uint32_t* a = (const uint32_t*)af;
#pragma unroll
            for (int nf = 0; nf < 8; nf++) {
                float bf[2];
                int f0 = wn + nf*8 + rl;
                bf[0] = sB[f0*LPAD + kb];
                bf[1] = sB[f0*LPAD + kb + 4];
                mma_tf32(acc[nf], a, (const uint32_t*)bf);
            }
        }
        float* gout = g_Tx2r + (size_t)s*NN*HH;
#pragma unroll
        for (int nf = 0; nf < 8; nf++) {
            int f = wn + nf*8 + cl;
            if (m0r < NN)
                *(float2*)(gout + (size_t)m0r*HH + f) =
                    make_float2(tf32r(acc[nf][0]), tf32r(acc[nf][1]));
            if (m1r < NN)
                *(float2*)(gout + (size_t)m1r*HH + f) =
                    make_float2(tf32r(acc[nf][2]), tf32r(acc[nf][3]));
        }
    }
}

// -------- K3b: weight prep --------
__global__ void prep_w_kernel(const float* __restrict__ chw,
                              const float* __restrict__ w1,
                              const float* __restrict__ w2,
                              const float* __restrict__ w3)
{
    int idx = blockIdx.x*256 + threadIdx.x;
    if (idx < 128*384) {
        int n = idx / 384, k = idx % 384;
        g_WchebT[idx] = tf32r(chw[k*128 + n]);
    }
    if (idx < 192*384) {
        int j = idx / 384, k = idx % 384;
        int v = j >> 6, co = j & 63;
        const float* w = (v == 0) ? w1 : (v == 1 ? w2 : w3);
        g_WcatT[idx] = tf32r(w[k*64 + co]);
    }
}

// -------- K4: cheb einsum GEMM, tf32 mma, 2-stage pipeline, 2 CTA/SM --------
__global__ __launch_bounds__(256, 2)
void cheb_mma_kernel(const float* __restrict__ bias)
{
    extern __shared__ __align__(1024) float dynS[];

    int tid = threadIdx.x;
    int wid = tid >> 5, lane = tid & 31;
    int wm = (wid >> 2) * 64;
    int wn = (wid & 3) * 32;
    size_t m0 = (size_t)blockIdx.x * 128;

    float acc[4][4][4];
#pragma unroll
    for (int i = 0; i < 4; i++)
#pragma unroll
        for (int j = 0; j < 4; j++)
#pragma unroll
            for (int r = 0; r < 4; r++) acc[i][j][r] = 0.f;

    auto issue = [&](int c, int stage){
        float* sAf = dynS + stage*8192;
        float* sBf = sAf + 4096;
        uint32_t sa = smem_u32(sAf), sb = smem_u32(sBf);
        const float* Am = (c < 4) ? g_T0r : (c < 8 ? g_Tx1r : g_Tx2r);
        int k0 = (c & 3) * 32;
#pragma unroll
        for (int i = 0; i < 4; i++) {
            int u = tid + i*256;
            int row = u >> 3, un = u & 7;
            cp16(sa + swz128((uint32_t)(row*128 + un*16)),
                 Am + (m0 + row)*HH + k0 + un*4);
        }
#pragma unroll
        for (int i = 0; i < 4; i++) {
            int u = tid + i*256;
            int row = u >> 3, un = u & 7;
            cp16(sb + swz128((uint32_t)(row*128 + un*16)),
                 g_WchebT + (size_t)row*384 + c*32 + un*4);
        }
        asm volatile("cp.async.commit_group;");
    };

    issue(0, 0);
    for (int c = 0; c < 12; c++) {
        if (c < 11) {
            issue(c+1, (c+1)&1);
            asm volatile("cp.async.wait_group 1;");
        } else {
            asm volatile("cp.async.wait_group 0;");
        }
        __syncthreads();
        const uint32_t* sAu = (const uint32_t*)(dynS + (c&1)*8192);
        const uint32_t* sBu = sAu + 4096;

#pragma unroll
        for (int k8 = 0; k8 < 4; k8++) {
            int kb = k8*8 + (lane & 3);
            uint32_t a[4][4], b[4][2];
#pragma unroll
            for (int mf = 0; mf < 4; mf++) {
                int r0 = wm + mf*16 + (lane >> 2);
                a[mf][0] = sAu[swzw(r0,     kb)];
                a[mf][1] = sAu[swzw(r0 + 8, kb)];
                a[mf][2] = sAu[swzw(r0,     kb + 4)];
                a[mf][3] = sAu[swzw(r0 + 8, kb + 4)];
            }
#pragma unroll
            for (int nf = 0; nf < 4; nf++) {
                int n0 = wn + nf*8 + (lane >> 2);
                b[nf][0] = sBu[swzw(n0, kb)];
                b[nf][1] = sBu[swzw(n0, kb + 4)];
            }
#pragma unroll
            for (int mf = 0; mf < 4; mf++)
#pragma unroll
                for (int nf = 0; nf < 4; nf++)
                    mma_tf32(acc[mf][nf], a[mf], b[nf]);
        }
        __syncthreads();
    }

    int rl = lane >> 2, cl = (lane & 3)*2;
#pragma unroll
    for (int mf = 0; mf < 4; mf++) {
        size_t mrow = m0 + wm + mf*16 + rl;
#pragma unroll
        for (int nf = 0; nf < 4; nf++) {
            int n = wn + nf*8 + cl;
            float bv0 = bias[n], bv1 = bias[n+1];
            float v00 = acc[mf][nf][0] + bv0; v00 = v00 > 0.f ? v00 : 0.f;
            float v01 = acc[mf][nf][1] + bv1; v01 = v01 > 0.f ? v01 : 0.f;
            float v10 = acc[mf][nf][2] + bv0; v10 = v10 > 0.f ? v10 : 0.f;
            float v11 = acc[mf][nf][3] + bv1; v11 = v11 > 0.f ? v11 : 0.f;
            *reinterpret_cast<float2*>(&g_Gr[mrow*HH + n]) =
                make_float2(tf32r(v00), tf32r(v01));
            *reinterpret_cast<float2*>(&g_Gr[(mrow+8)*HH + n]) =
                make_float2(tf32r(v10), tf32r(v11));
        }
    }
}

// -------- K5: tconv2 GEMM, M-tile 64, tf32 mma, 2-stage pipeline + gating --------
// grid MT2/64 = 900. 8 warps: wm=(wid>>2)*32 (2 m-groups), cg=wid&3 (16-co group).
// acc[2][3][2][4] = 48 regs. smem/stage = A 2048 + B 6144 floats = 32 KB.
__global__ __launch_bounds__(256, 2)
void tconv2_mma_kernel(const float* __restrict__ b1,
                       const float* __restrict__ b2,
                       const float* __restrict__ b3)
{
    extern __shared__ __align__(1024) float dynS[];

    int tid = threadIdx.x;
    int wid = tid >> 5, lane = tid & 31;
    int wm = (wid >> 2) * 32;
    int cg = wid & 3;
    int m0 = blockIdx.x * 64;

    float acc[2][3][2][4];
#pragma unroll
    for (int i = 0; i < 2; i++)
#pragma unroll
        for (int v = 0; v < 3; v++)
#pragma unroll
            for (int cf = 0; cf < 2; cf++)
#pragma unroll
                for (int r = 0; r < 4; r++) acc[i][v][cf][r] = 0.f;

    auto issue = [&](int c, int stage){
        float* sAf = dynS + stage*8192;
        float* sBf = sAf + 2048;
        uint32_t sa = smem_u32(sAf), sb = smem_u32(sBf);
        int kt = c >> 2;
        int k0 = (c & 3) * 32;
#pragma unroll
        for (int i = 0; i < 2; i++) {                 // A: 512 units
            int u = tid + i*256;
            int row = u >> 3, un = u & 7;
            int gm = m0 + row;
            int t = gm % 36, n = (gm/36) % 50, b = gm / 1800;
            cp16(sa + swz128((uint32_t)(row*128 + un*16)),
                 g_Gr + (((size_t)(b*T1 + t + kt))*NN + n)*HH + k0 + un*4);
        }
#pragma unroll
        for (int i = 0; i < 6; i++) {                 // B: 1536 units
            int u = tid + i*256;
            int row = u >> 3, un = u & 7;
            cp16(sb + swz128((uint32_t)(row*128 + un*16)),
                 g_WcatT + (size_t)row*384 + c*32 + un*4);
        }
        asm volatile("cp.async.commit_group;");
    };

    issue(0, 0);
    for (int c = 0; c < 12; c++) {
        if (c < 11) {
            issue(c+1, (c+1)&1);
            asm volatile("cp.async.wait_group 1;");
        } else {
            asm volatile("cp.async.wait_group 0;");
        }
        __syncthreads();
        const uint32_t* sAu = (const uint32_t*)(dynS + (c&1)*8192);
        const uint32_t* sBu = sAu + 2048;

#pragma unroll
        for (int k8 = 0; k8 < 4; k8++) {
            int kb = k8*8 + (lane & 3);
            uint32_t a[2][4], b[6][2];
#pragma unroll
            for (int mf = 0; mf < 2; mf++) {
                int r0 = wm + mf*16 + (lane >> 2);
                a[mf][0] = sAu[swzw(r0,     kb)];
                a[mf][1] = sAu[swzw(r0 + 8, kb)];
                a[mf][2] = sAu[swzw(r0,     kb + 4)];
                a[mf][3] = sAu[swzw(r0 + 8, kb + 4)];
            }
#pragma unroll
            for (int v = 0; v < 3; v++)
#pragma unroll
                for (int cf = 0; cf < 2; cf++) {
                    int nrow = v*64 + cg*16 + cf*8 + (lane >> 2);
                    b[v*2+cf][0] = sBu[swzw(nrow, kb)];
                    b[v*2+cf][1] = sBu[swzw(nrow, kb + 4)];
                }
#pragma unroll
            for (int mf = 0; mf < 2; mf++)
#pragma unroll
                for (int v = 0; v < 3; v++)
#pragma unroll
                    for (int cf = 0; cf < 2; cf++)
                        mma_tf32(acc[mf][v][cf], a[mf], b[v*2+cf]);
        }
        __syncthreads();
    }

    int rl = lane >> 2, cl = (lane & 3)*2;
#pragma unroll
    for (int mf = 0; mf < 2; mf++) {
#pragma unroll
        for (int h = 0; h < 2; h++) {
            int gm = m0 + wm + mf*16 + rl + h*8;
            int t = gm % 36, n = (gm/36) % 50, b = gm / 1800;
            float* dst = g_T2 + (((size_t)(b*T2T + t))*NN + n)*CO;
#pragma unroll
            for (int cf = 0; cf < 2; cf++) {
                int co = cg*16 + cf*8 + cl;
                float p0 = acc[mf][0][cf][h*2+0] + b1[co];
                float p1 = acc[mf][0][cf][h*2+1] + b1[co+1];
                float q0 = acc[mf][1][cf][h*2+0] + b2[co];
                float q1 = acc[mf][1][cf][h*2+1] + b2[co+1];
                float r0 = acc[mf][2][cf][h*2+0] + b3[co];
                float r1 = acc[mf][2][cf][h*2+1] + b3[co+1];
                float v0 = p0 * sigm(q0) + r0; v0 = v0 > 0.f ? v0 : 0.f;
                float v1 = p1 * sigm(q1) + r1; v1 = v1 > 0.f ? v1 : 0.f;
                *reinterpret_cast<float2*>(dst + co) = make_float2(v0, v1);
            }
        }
    }
}

// -------- K6a/b: BN stats --------
__global__ void bn_part_kernel()
{
    int n = blockIdx.x, q = blockIdx.y;
    int tid = threadIdx.x;
    const int CH = BB*T2T/4;
    double s = 0.0, s2 = 0.0;
    for (int i = tid; i < CH*CO; i += 256) {
        int bt = q*CH + (i >> 6), co = i & 63;
        float v = g_T2[((size_t)bt*NN + n)*CO + co];
        s += v; s2 += (double)v*v;
    }
    __shared__ double shs[256], shs2[256];
    shs[tid] = s; shs2[tid] = s2;
    __syncthreads();
    for (int stp = 128; stp > 0; stp >>= 1) {
        if (tid < stp) { shs[tid] += shs[tid+stp]; shs2[tid] += shs2[tid+stp]; }
        __syncthreads();
    }
    if (tid == 0) { g_bnPart[q][n][0] = shs[0]; g_bnPart[q][n][1] = shs2[0]; }
}

__global__ void bn_final_kernel(const float* __restrict__ gamma,
                                const float* __restrict__ beta)
{
    int n = threadIdx.x;
    if (n < NN) {
        double s = 0.0, s2 = 0.0;
#pragma unroll
        for (int q = 0; q < 4; q++) { s += g_bnPart[q][n][0]; s2 += g_bnPart[q][n][1]; }
        const double M = (double)(BB*T2T*CO);
        double mean = s / M;
        double var  = s2 / M - mean*mean;
        float rstd = (float)(1.0 / sqrt(var + 1e-5));
        float a = rstd * gamma[n];
        g_bnA[n] = a;
        g_bnC[n] = beta[n] - (float)mean * a;
    }
}

// -------- K7: window sums with BN folded --------
__global__ void swin_kernel()
{
    int b = blockIdx.x;
    int j = blockIdx.y*128 + threadIdx.x;
    const float* base = g_T2 + (size_t)b*T2T*3200 + j;
    float tot = 0.f, v0 = 0.f, v1 = 0.f, v34 = 0.f, v35 = 0.f;
#pragma unroll
    for (int t = 0; t < T2T; t++) {
        float v = base[(size_t)t*3200];
        tot += v;
        if (t == 0)  v0  = v;
        if (t == 1)  v1  = v;
        if (t == 34) v34 = v;
        if (t == 35) v35 = v;
    }
    int n = j >> 6;
    float a = g_bnA[n], c = 34.f * g_bnC[n];
    g_S[((size_t)b*3 + 0)*3200 + j] = a*(tot - v34 - v35) + c;
    g_S[((size_t)b*3 + 1)*3200 + j] = a*(tot - v0  - v35) + c;
    g_S[((size_t)b*3 + 2)*3200 + j] = a*(tot - v0  - v1 ) + c;
}

// -------- K8a: pooled split-K partials --------
__global__ void pooled_part_kernel(const float* __restrict__ w)
{
    extern __shared__ float psm[];
    float* sS = psm;                 // 32*385
    float* sw = psm + 32*385;        // 16*384

    int kp = blockIdx.x, og = blockIdx.y;
    int tid = threadIdx.x;

    for (int idx = tid; idx < 32*384; idx += 256) {
        int b = idx / 384, kk = idx % 384;
        sS[b*385 + kk] = g_S[(size_t)b*9600 + kp*384 + kk];
    }
    for (int idx = tid; idx < 16*384; idx += 256) {
        int o = idx / 384, kk = idx % 384;
        sw[idx] = w[(size_t)(og*16 + o)*9600 + kp*384 + kk];
    }
    __syncthreads();

    int ol = tid >> 4, bp = tid & 15;
    const float* wr = sw + ol*384;
    const float* s0 = sS + (2*bp)*385;
    const float* s1 = sS + (2*bp+1)*385;
    float a0 = 0.f, a1 = 0.f;
#pragma unroll 8
    for (int kk = 0; kk < 384; kk++) {
        float wv = wr[kk];
        a0 += wv * s0[kk];
        a1 += wv * s1[kk];
    }
    g_poolPart[kp][og*16 + ol][2*bp]   = a0;
    g_poolPart[kp][og*16 + ol][2*bp+1] = a1;
}

// -------- K8b: pooled finalize --------
__global__ void pooled_final_kernel(const float* __restrict__ cb)
{
    int idx = blockIdx.x*256 + threadIdx.x;
    if (idx >= 128*32) return;
    int o = idx >> 5, b = idx & 31;
    float s = 0.f;
#pragma unroll
    for (int kp = 0; kp < 25; kp++)
        s += g_poolPart[kp][o][b];
    g_pooled[b*128 + o] = s * (1.f/34.f) + cb[o];
}

// -------- K9: fc --------
__global__ void fc_kernel(const float* __restrict__ f1w,
                          const float* __restrict__ f1b,
                          float* __restrict__ out)
{
    int q  = blockIdx.x*128 + threadIdx.x;
    int bg = blockIdx.y;
    __shared__ float sp[8*128];
    for (int i = threadIdx.x; i < 8*128; i += 128)
        sp[i] = g_pooled[bg*8*128 + i];
    __syncthreads();

    float acc[8];
#pragma unroll
    for (int b = 0; b < 8; b++) acc[b] = 0.f;
#pragma unroll 4
    for (int o = 0; o < 128; o++) {
        float wv = f1w[(size_t)o*3200 + q];
#pragma unroll
        for (int b = 0; b < 8; b++)
            acc[b] += sp[b*128 + o] * wv;
    }
    float bias = f1b[q];
#pragma unroll
    for (int b = 0; b < 8; b++)
        out[(size_t)(bg*8 + b)*3200 + q] = acc[b] + bias;
}

// ---------------- launch ----------------
extern "C" void kernel_launch(void* const* d_in, const int* in_sizes, int n_in,
                              void* d_out, int out_size)
{
    int iEI, iT1W1, iT1B1, iT1W2, iT1B2, iT1W3, iT1B3, iCW, iCB;
    int iT2W1, iT2B1, iT2W2, iT2B2, iT2W3, iT2B3, iGam, iBet, iC3W, iC3B, iF1W, iF1B;
    if (n_in > 1 && in_sizes[1] == BB*TW*2*EE) {
        iEI=1;  iT1W1=2;  iT1B1=3;  iT1W2=4;  iT1B2=5;  iT1W3=6;  iT1B3=7;
        iCW=8;  iCB=9;
        iT2W1=10; iT2B1=11; iT2W2=12; iT2B2=13; iT2W3=14; iT2B3=15;
        iGam=16; iBet=17; iC3W=18; iC3B=19; iF1W=20; iF1B=21;
    } else {
        iT1W1=1;  iT1B1=2;  iT1W2=3;  iT1B2=4;  iT1W3=5;  iT1B3=6;
        iCW=7;  iCB=8;
        iT2W1=9;  iT2B1=10; iT2W2=11; iT2B2=12; iT2W3=13; iT2B3=14;
        iGam=15; iBet=16; iC3W=17; iC3B=18; iF1W=19; iF1B=20; iEI=21;
    }

    const float* X    = (const float*)d_in[0];
    const int*   EI   = (const int*)  d_in[iEI];
    const float* t1w1 = (const float*)d_in[iT1W1];
    const float* t1b1 = (const float*)d_in[iT1B1];
    const float* t1w2 = (const float*)d_in[iT1W2];
    const float* t1b2 = (const float*)d_in[iT1B2];
    const float* t1w3 = (const float*)d_in[iT1W3];
    const float* t1b3 = (const float*)d_in[iT1B3];
    const float* chw  = (const float*)d_in[iCW];
    const float* chb  = (const float*)d_in[iCB];
    const float* t2w1 = (const float*)d_in[iT2W1];
    const float* t2b1 = (const float*)d_in[iT2B1];
    const float* t2w2 = (const float*)d_in[iT2W2];
    const float* t2b2 = (const float*)d_in[iT2B2];
    const float* t2w3 = (const float*)d_in[iT2W3];
    const float* t2b3 = (const float*)d_in[iT2B3];
    const float* gam  = (const float*)d_in[iGam];
    const float* bet  = (const float*)d_in[iBet];
    const float* c3w  = (const float*)d_in[iC3W];
    const float* c3b  = (const float*)d_in[iC3B];
    const float* f1w  = (const float*)d_in[iF1W];
    const float* f1b  = (const float*)d_in[iF1B];
    float* out = (float*)d_out;

    static const int PROP_SMEM  = (64 + 128) * LPAD * 4;             // 52,224 B
    static const int CHEB_SMEM  = 2*8192*4;                          // 65,536 B
    static const int T2_SMEM    = 2*8192*4;                          // 65,536 B
    static const int POOL_SMEM  = (32*385 + 16*384)*4;               // 73,856 B
    cudaFuncSetAttribute(prop_dense_kernel,
                         cudaFuncAttributeMaxDynamicSharedMemorySize, PROP_SMEM);
    cudaFuncSetAttribute(cheb_mma_kernel,
                         cudaFuncAttributeMaxDynamicSharedMemorySize, CHEB_SMEM);
    cudaFuncSetAttribute(tconv2_mma_kernel,
                         cudaFuncAttributeMaxDynamicSharedMemorySize, T2_SMEM);
    cudaFuncSetAttribute(pooled_part_kernel,
                         cudaFuncAttributeMaxDynamicSharedMemorySize, POOL_SMEM);

    tconv1_kernel<<<NSL, 128>>>(X, t1w1, t1b1, t1w2, t1b2, t1w3, t1b3);
    prep_w_kernel<<<(192*384 + 255)/256, 256>>>(chw, t2w1, t2w2, t2w3);
    prop_dense_kernel<<<NSL, 256, PROP_SMEM>>>(EI);
    cheb_mma_kernel<<<MCHEB/128, 256, CHEB_SMEM>>>(chb);
    tconv2_mma_kernel<<<MT2/64, 256, T2_SMEM>>>(t2b1, t2b2, t2b3);
    bn_part_kernel<<<dim3(NN, 4), 256>>>();
    bn_final_kernel<<<1, 64>>>(gam, bet);
    swin_kernel<<<dim3(BB, 25), 128>>>();
    pooled_part_kernel<<<dim3(25, 8), 256, POOL_SMEM>>>(c3w);
    pooled_final_kernel<<<16, 256>>>(c3b);
    fc_kernel<<<dim3(25, 4), 128>>>(f1w, f1b, out);
}

// round 13
// speedup vs baseline: 1.1979x; 1.1979x over previous
#include <cuda_runtime.h>
#include <cuda_bf16.h>
#include <math.h>
#include <stdint.h>

// ---------------- problem constants ----------------
#define BB   32
#define TW   40
#define T1   38
#define T2T  36
#define NN   50
#define CIN  2
#define HH   128
#define CO   64
#define EE   800
#define NSL  (BB*T1)        // 1216
#define MCHEB (NSL*NN)      // 60800
#define MT2   (BB*NN*T2T)   // 57600
#define LPAD 68

// ---------------- scratch ----------------
__device__ float g_T0r [(size_t)NSL*NN*HH];
__device__ float g_Tx1r[(size_t)NSL*NN*HH];
__device__ float g_Tx2r[(size_t)NSL*NN*HH];
__device__ float g_Gr  [(size_t)NSL*NN*HH];
__device__ float g_T2  [BB*T2T*NN*CO];
__device__ float g_WchebT[128*384];
__device__ float g_WcatT [192*384];
__device__ double g_bnPart[4][NN][2];
__device__ float g_bnA[NN];
__device__ float g_bnC[NN];
__device__ float g_S[BB*3*3200];
__device__ float g_poolPart[25][128][32];
__device__ float g_pooled[BB*128];

__device__ __forceinline__ float sigm(float x){ return 1.f/(1.f+__expf(-x)); }
__device__ __forceinline__ float tf32r(float x){
    uint32_t r; asm("cvt.rna.tf32.f32 %0, %1;" : "=r"(r) : "f"(x));
    return __uint_as_float(r);
}

// ---------------- PTX helpers ----------------
__device__ __forceinline__ uint32_t smem_u32(const void* p){
    uint32_t a;
    asm("{ .reg .u64 t; cvta.to.shared.u64 t, %1; cvt.u32.u64 %0, t; }" : "=r"(a) : "l"(p));
    return a;
}
__device__ __forceinline__ uint32_t swz128(uint32_t off){ return off ^ ((off >> 3) & 0x70); }
__device__ __forceinline__ void cp16(uint32_t dst, const void* src){
    asm volatile("cp.async.cg.shared.global [%0], [%1], 16;" :: "r"(dst), "l"(src));
}
__device__ __forceinline__ void mma_tf32(float* c, const uint32_t* a, const uint32_t* b){
    asm volatile("mma.sync.aligned.m16n8k8.row.col.f32.tf32.tf32.f32 "
        "{%0,%1,%2,%3}, {%4,%5,%6,%7}, {%8,%9}, {%0,%1,%2,%3};"
        : "+f"(c[0]), "+f"(c[1]), "+f"(c[2]), "+f"(c[3])
        : "r"(a[0]),"r"(a[1]),"r"(a[2]),"r"(a[3]), "r"(b[0]),"r"(b[1]));
}
__device__ __forceinline__ uint32_t swzw(int row, int k){
    return swz128((uint32_t)(row*128 + k*4)) >> 2;
}

// ---------------- K1: temporal gated conv 1 ----------------
__global__ void tconv1_kernel(const float* __restrict__ X,
                              const float* __restrict__ w1, const float* __restrict__ b1,
                              const float* __restrict__ w2, const float* __restrict__ b2,
                              const float* __restrict__ w3, const float* __restrict__ b3)
{
    int s = blockIdx.x;
    int b = s / T1, t = s % T1;
    int h = threadIdx.x;
    float W1[6], W2[6], W3[6];
#pragma unroll
    for (int i = 0; i < 6; i++) {
        W1[i] = w1[i*128 + h]; W2[i] = w2[i*128 + h]; W3[i] = w3[i*128 + h];
    }
    float bb1 = b1[h], bb2 = b2[h], bb3 = b3[h];

    __shared__ float xs[3][NN*CIN];
    for (int i = threadIdx.x; i < 3*NN*CIN; i += 128) {
        int kt = i / (NN*CIN), rem = i % (NN*CIN);
        xs[kt][rem] = X[((size_t)(b*TW + t + kt)*NN)*CIN + rem];
    }
    __syncthreads();

    size_t ob = ((size_t)s*NN)*HH + h;
    for (int n = 0; n < NN; n++) {
        float p = bb1, q = bb2, r = bb3;
#pragma unroll
        for (int kt = 0; kt < 3; kt++)
#pragma unroll
            for (int c = 0; c < 2; c++) {
                float xv = xs[kt][n*2 + c];
                p += xv * W1[kt*2 + c]; q += xv * W2[kt*2 + c]; r += xv * W3[kt*2 + c];
            }
        float v = p * sigm(q) + r;
        v = v > 0.f ? v : 0.f;
        g_T0r[ob + (size_t)n*HH] = tf32r(v);
    }
}

// -------- K3: fused edge-prep + dense Chebyshev propagation via tf32 MMA --------
__global__ __launch_bounds__(256, 3)
void prop_dense_kernel(const int* __restrict__ ei)
{
    extern __shared__ __align__(16) float dyn[];
    float* sA = dyn;                  // 64*68: dense L (rows >= 50 stay 0)
    float* sB = dyn + 64*LPAD;        // 128*68: T0^T, then 2*Tx1^T
    __shared__ int   deg[NN];
    __shared__ float dis[NN];

    int s = blockIdx.x;
    int b = s / T1, t = s % T1;
    int tid = threadIdx.x;
    int wid = tid >> 5, lane = tid & 31;
    int wm = (wid & 3) * 16;
    int wn = (wid >> 2) * 64;

    const int* row = ei + (size_t)(b*TW + t)*(2*EE);
    const int* col = row + EE;
    const float* t0p = g_T0r + (size_t)s*NN*HH;

    for (int i = tid; i < 64*LPAD; i += 256) sA[i] = 0.f;
    if (tid < NN) deg[tid] = 0;
    __syncthreads();

    for (int e = tid; e < EE; e += 256) atomicAdd(&deg[row[e]], 1);
    for (int i = tid; i < NN*HH; i += 256) {
        int c = i >> 7, f = i & 127;
        sB[f*LPAD + c] = t0p[i];
    }
    for (int i = tid; i < 128*(LPAD-NN); i += 256) {
        int f = i / (LPAD-NN), c = NN + i % (LPAD-NN);
        sB[f*LPAD + c] = 0.f;
    }
    __syncthreads();
    if (tid < NN) dis[tid] = deg[tid] > 0 ? rsqrtf((float)deg[tid]) : 0.f;
    __syncthreads();
    for (int e = tid; e < EE; e += 256) {
        int r = row[e], c = col[e];
        atomicAdd(&sA[r*LPAD + c], -dis[r]*dis[c]);
    }
    __syncthreads();
    for (int i = tid; i < NN*64; i += 256) {
        int n = i >> 6, c = i & 63;
        sA[n*LPAD + c] = tf32r(sA[n*LPAD + c]);
    }
    __syncthreads();

    int rl = lane >> 2, cl = (lane & 3)*2;
    int m0r = wm + rl, m1r = wm + rl + 8;

    // ---- phase 1: acc = L @ T0 ----
    {
        float acc[8][4];
#pragma unroll
        for (int nf = 0; nf < 8; nf++)
#pragma unroll
            for (int r = 0; r < 4; r++) acc[nf][r] = 0.f;
#pragma unroll
        for (int k8 = 0; k8 < 8; k8++) {
            int kb = k8*8 + (lane & 3);
            float af[4];
            af[0] = sA[m0r*LPAD + kb];
            af[1] = sA[m1r*LPAD + kb];
            af[2] = sA[m0r*LPAD + kb + 4];
            af[3] = sA[m1r*LPAD + kb + 4];
            const uint32_t* a = (const uint32_t*)af;
#pragma unroll
            for (int nf = 0; nf < 8; nf++) {
                float bf[2];
                int f0 = wn + nf*8 + rl;
                bf[0] = sB[f0*LPAD + kb];
                bf[1] = sB[f0*LPAD + kb + 4];
                mma_tf32(acc[nf], a, (const uint32_t*)bf);
            }
        }
        __syncthreads();
        float* gout = g_Tx1r + (size_t)s*NN*HH;
#pragma unroll
        for (int nf = 0; nf < 8; nf++) {
            int f = wn + nf*8 + cl;
            sB[f*LPAD + m0r]     = 2.f*acc[nf][0];
            sB[(f+1)*LPAD + m0r] = 2.f*acc[nf][1];
            sB[f*LPAD + m1r]     = 2.f*acc[nf][2];
            sB[(f+1)*LPAD + m1r] = 2.f*acc[nf][3];
            if (m0r < NN)
                *(float2*)(gout + (size_t)m0r*HH + f) =
                    make_float2(tf32r(acc[nf][0]), tf32r(acc[nf][1]));
            if (m1r < NN)
                *(float2*)(gout + (size_t)m1r*HH + f) =
                    make_float2(tf32r(acc[nf][2]), tf32r(acc[nf][3]));
        }
    }
    __syncthreads();

    // ---- phase 2: acc = -T0 + L @ (2*Tx1) ----
    {
        float acc[8][4];
#pragma unroll
        for (int nf = 0; nf < 8; nf++) {
            int f = wn + nf*8 + cl;
            if (m0r < NN) {
                float2 v = *(const float2*)(t0p + (size_t)m0r*HH + f);
                acc[nf][0] = -v.x; acc[nf][1] = -v.y;
            } else { acc[nf][0] = 0.f; acc[nf][1] = 0.f; }
            if (m1r < NN) {
                float2 v = *(const float2*)(t0p + (size_t)m1r*HH + f);
                acc[nf][2] = -v.x; acc[nf][3] = -v.y;
            } else { acc[nf][2] = 0.f; acc[nf][3] = 0.f; }
        }
#pragma unroll
        for (int k8 = 0; k8 < 8; k8++) {
            int kb = k8*8 + (lane & 3);
            float af[4];
            af[0] = sA[m0r*LPAD + kb];
            af[1] = sA[m1r*LPAD + kb];
            af[2] = sA[m0r*LPAD + kb + 4];
            af[3] = sA[m1r*LPAD + kb + 4];
            const uint32_t* a = (const uint32_t*)af;
#pragma unroll
            for (int nf = 0; nf < 8; nf++) {
                float bf[2];
                int f0 = wn + nf*8 + rl;
                bf[0] = sB[f0*LPAD + kb];
                bf[1] = sB[f0*LPAD + kb + 4];
                mma_tf32(acc[nf], a, (const uint32_t*)bf);
            }
        }
        float* gout = g_Tx2r + (size_t)s*NN*HH;
#pragma unroll
        for (int nf = 0; nf < 8; nf++) {
            int f = wn + nf*8 + cl;
            if (m0r < NN)
                *(float2*)(gout + (size_t)m0r*HH + f) =
                    make_float2(tf32r(acc[nf][0]), tf32r(acc[nf][1]));
            if (m1r < NN)
                *(float2*)(gout + (size_t)m1r*HH + f) =
                    make_float2(tf32r(acc[nf][2]), tf32r(acc[nf][3]));
        }
    }
}

// -------- K3b: weight prep --------
__global__ void prep_w_kernel(const float* __restrict__ chw,
                              const float* __restrict__ w1,
                              const float* __restrict__ w2,
                              const float* __restrict__ w3)
{
    int idx = blockIdx.x*256 + threadIdx.x;
    if (idx < 128*384) {
        int n = idx / 384, k = idx % 384;
        g_WchebT[idx] = tf32r(chw[k*128 + n]);
    }
    if (idx < 192*384) {
        int j = idx / 384, k = idx % 384;
        int v = j >> 6, co = j & 63;
        const float* w = (v == 0) ? w1 : (v == 1 ? w2 : w3);
        g_WcatT[idx] = tf32r(w[k*64 + co]);
    }
}

// -------- K4: cheb einsum GEMM, tf32 mma, 3-stage cp.async pipeline --------
__global__ __launch_bounds__(256, 1)
void cheb_mma_kernel(const float* __restrict__ bias)
{
    extern __shared__ __align__(1024) float dynS[];

    int tid = threadIdx.x;
    int wid = tid >> 5, lane = tid & 31;
    int wm = (wid >> 2) * 64;
    int wn = (wid & 3) * 32;
    size_t m0 = (size_t)blockIdx.x * 128;

    float acc[4][4][4];
#pragma unroll
    for (int i = 0; i < 4; i++)
#pragma unroll
        for (int j = 0; j < 4; j++)
#pragma unroll
            for (int r = 0; r < 4; r++) acc[i][j][r] = 0.f;

    auto issue = [&](int c, int stage){
        float* sAf = dynS + stage*8192;
        float* sBf = sAf + 4096;
        uint32_t sa = smem_u32(sAf), sb = smem_u32(sBf);
        const float* Am = (c < 4) ? g_T0r : (c < 8 ? g_Tx1r : g_Tx2r);
        int k0 = (c & 3) * 32;
#pragma unroll
        for (int i = 0; i < 4; i++) {
            int u = tid + i*256;
            int row = u >> 3, un = u & 7;
            cp16(sa + swz128((uint32_t)(row*128 + un*16)),
                 Am + (m0 + row)*HH + k0 + un*4);
        }
#pragma unroll
        for (int i = 0; i < 4; i++) {
            int u = tid + i*256;
            int row = u >> 3, un = u & 7;
            cp16(sb + swz128((uint32_t)(row*128 + un*16)),
                 g_WchebT + (size_t)row*384 + c*32 + un*4);
        }
        asm volatile("cp.async.commit_group;");
    };

    issue(0, 0);
    issue(1, 1);
    for (int c = 0; c < 12; c++) {
        if (c + 2 < 12) {
            issue(c+2, (c+2)%3);
            asm volatile("cp.async.wait_group 2;");
        } else if (c + 1 < 12) {
            asm volatile("cp.async.wait_group 1;");
        } else {
            asm volatile("cp.async.wait_group 0;");
        }
        __syncthreads();
        const uint32_t* sAu = (const uint32_t*)(dynS + (c%3)*8192);
        const uint32_t* sBu = sAu + 4096;

#pragma unroll
        for (int k8 = 0; k8 < 4; k8++) {
            int kb = k8*8 + (lane & 3);
            uint32_t a[4][4], b[4][2];
#pragma unroll
            for (int mf = 0; mf < 4; mf++) {
                int r0 = wm + mf*16 + (lane >> 2);
                a[mf][0] = sAu[swzw(r0,     kb)];
                a[mf][1] = sAu[swzw(r0 + 8, kb)];
                a[mf][2] = sAu[swzw(r0,     kb + 4)];
                a[mf][3] = sAu[swzw(r0 + 8, kb + 4)];
            }
#pragma unroll
            for (int nf = 0; nf < 4; nf++) {
                int n0 = wn + nf*8 + (lane >> 2);
                b[nf][0] = sBu[swzw(n0, kb)];
                b[nf][1] = sBu[swzw(n0, kb + 4)];
            }
#pragma unroll
            for (int mf = 0; mf < 4; mf++)
#pragma unroll
                for (int nf = 0; nf < 4; nf++)
                    mma_tf32(acc[mf][nf], a[mf], b[nf]);
        }
        __syncthreads();
    }

    int rl = lane >> 2, cl = (lane & 3)*2;
#pragma unroll
    for (int mf = 0; mf < 4; mf++) {
        size_t mrow = m0 + wm + mf*16 + rl;
#pragma unroll
        for (int nf = 0; nf < 4; nf++) {
            int n = wn + nf*8 + cl;
            float bv0 = bias[n], bv1 = bias[n+1];
            float v00 = acc[mf][nf][0] + bv0; v00 = v00 > 0.f ? v00 : 0.f;
            float v01 = acc[mf][nf][1] + bv1; v01 = v01 > 0.f ? v01 : 0.f;
            float v10 = acc[mf][nf][2] + bv0; v10 = v10 > 0.f ? v10 : 0.f;
            float v11 = acc[mf][nf][3] + bv1; v11 = v11 > 0.f ? v11 : 0.f;
            *reinterpret_cast<float2*>(&g_Gr[mrow*HH + n]) =
                make_float2(tf32r(v00), tf32r(v01));
            *reinterpret_cast<float2*>(&g_Gr[(mrow+8)*HH + n]) =
                make_float2(tf32r(v10), tf32r(v11));
        }
    }
}

// -------- K5: tconv2 GEMM (M-tile 128), tf32 mma, 3-stage pipeline + gating --------
__global__ __launch_bounds__(256, 1)
void tconv2_mma_kernel(const float* __restrict__ b1,
                       const float* __restrict__ b2,
                       const float* __restrict__ b3)
{
    extern __shared__ __align__(1024) float dynS[];

    int tid = threadIdx.x;
    int wid = tid >> 5, lane = tid & 31;
    int wm = (wid >> 2) * 64;
    int cg = wid & 3;
    int m0 = blockIdx.x * 128;

    float acc[4][3][2][4];
#pragma unroll
    for (int i = 0; i < 4; i++)
#pragma unroll
        for (int v = 0; v < 3; v++)
#pragma unroll
            for (int cf = 0; cf < 2; cf++)
#pragma unroll
                for (int r = 0; r < 4; r++) acc[i][v][cf][r] = 0.f;

    auto issue = [&](int c, int stage){
        float* sAf = dynS + stage*10240;
        float* sBf = sAf + 4096;
        uint32_t sa = smem_u32(sAf), sb = smem_u32(sBf);
        int kt = c >> 2;
        int k0 = (c & 3) * 32;
#pragma unroll
        for (int i = 0; i < 4; i++) {
            int u = tid + i*256;
            int row = u >> 3, un = u & 7;
            int gm = m0 + row;
            int t = gm % 36, n = (gm/36) % 50, b = gm / 1800;
            cp16(sa + swz128((uint32_t)(row*128 + un*16)),
                 g_Gr + (((size_t)(b*T1 + t + kt))*NN + n)*HH + k0 + un*4);
        }
#pragma unroll
        for (int i = 0; i < 6; i++) {
            int u = tid + i*256;
            int row = u >> 3, un = u & 7;
            cp16(sb + swz128((uint32_t)(row*128 + un*16)),
                 g_WcatT + (size_t)row*384 + c*32 + un*4);
        }
        asm volatile("cp.async.commit_group;");
    };

    issue(0, 0);
    issue(1, 1);
    for (int c = 0; c < 12; c++) {
        if (c + 2 < 12) {
            issue(c+2, (c+2)%3);
            asm volatile("cp.async.wait_group 2;");
        } else if (c + 1 < 12) {
            asm volatile("cp.async.wait_group 1;");
        } else {
            asm volatile("cp.async.wait_group 0;");
        }
        __syncthreads();
        const uint32_t* sAu = (const uint32_t*)(dynS + (c%3)*10240);
        const uint32_t* sBu = sAu + 4096;

#pragma unroll
        for (int k8 = 0; k8 < 4; k8++) {
            int kb = k8*8 + (lane & 3);
            uint32_t a[4][4], b[6][2];
#pragma unroll
            for (int mf = 0; mf < 4; mf++) {
                int r0 = wm + mf*16 + (lane >> 2);
                a[mf][0] = sAu[swzw(r0,     kb)];
                a[mf][1] = sAu[swzw(r0 + 8, kb)];
                a[mf][2] = sAu[swzw(r0,     kb + 4)];
                a[mf][3] = sAu[swzw(r0 + 8, kb + 4)];
            }
#pragma unroll
            for (int v = 0; v < 3; v++)
#pragma unroll
                for (int cf = 0; cf < 2; cf++) {
                    int nrow = v*64 + cg*16 + cf*8 + (lane >> 2);
                    b[v*2+cf][0] = sBu[swzw(nrow, kb)];
                    b[v*2+cf][1] = sBu[swzw(nrow, kb + 4)];
                }
#pragma unroll
            for (int mf = 0; mf < 4; mf++)
#pragma unroll
                for (int v = 0; v < 3; v++)
#pragma unroll
                    for (int cf = 0; cf < 2; cf++)
                        mma_tf32(acc[mf][v][cf], a[mf], b[v*2+cf]);
        }
        __syncthreads();
    }

    int rl = lane >> 2, cl = (lane & 3)*2;
#pragma unroll
    for (int mf = 0; mf < 4; mf++) {
#pragma unroll
        for (int h = 0; h < 2; h++) {
            int gm = m0 + wm + mf*16 + rl + h*8;
            int t = gm % 36, n = (gm/36) % 50, b = gm / 1800;
            float* dst = g_T2 + (((size_t)(b*T2T + t))*NN + n)*CO;
#pragma unroll
            for (int cf = 0; cf < 2; cf++) {
                int co = cg*16 + cf*8 + cl;
                float p0 = acc[mf][0][cf][h*2+0] + b1[co];
                float p1 = acc[mf][0][cf][h*2+1] + b1[co+1];
                float q0 = acc[mf][1][cf][h*2+0] + b2[co];
                float q1 = acc[mf][1][cf][h*2+1] + b2[co+1];
                float r0 = acc[mf][2][cf][h*2+0] + b3[co];
                float r1 = acc[mf][2][cf][h*2+1] + b3[co+1];
                float v0 = p0 * sigm(q0) + r0; v0 = v0 > 0.f ? v0 : 0.f;
                float v1 = p1 * sigm(q1) + r1; v1 = v1 > 0.f ? v1 : 0.f;
                *reinterpret_cast<float2*>(dst + co) = make_float2(v0, v1);
            }
        }
    }
}

// -------- K6a/b: BN stats --------
__global__ void bn_part_kernel()
{
    int n = blockIdx.x, q = blockIdx.y;
    int tid = threadIdx.x;
    const int CH = BB*T2T/4;
    double s = 0.0, s2 = 0.0;
    for (int i = tid; i < CH*CO; i += 256) {
        int bt = q*CH + (i >> 6), co = i & 63;
        float v = g_T2[((size_t)bt*NN + n)*CO + co];
        s += v; s2 += (double)v*v;
    }
    __shared__ double shs[256], shs2[256];
    shs[tid] = s; shs2[tid] = s2;
    __syncthreads();
    for (int stp = 128; stp > 0; stp >>= 1) {
        if (tid < stp) { shs[tid] += shs[tid+stp]; shs2[tid] += shs2[tid+stp]; }
        __syncthreads();
    }
    if (tid == 0) { g_bnPart[q][n][0] = shs[0]; g_bnPart[q][n][1] = shs2[0]; }
}

__global__ void bn_final_kernel(const float* __restrict__ gamma,
                                const float* __restrict__ beta)
{
    int n = threadIdx.x;
    if (n < NN) {
        double s = 0.0, s2 = 0.0;
#pragma unroll
        for (int q = 0; q < 4; q++) { s += g_bnPart[q][n][0]; s2 += g_bnPart[q][n][1]; }
        const double M = (double)(BB*T2T*CO);
        double mean = s / M;
        double var  = s2 / M - mean*mean;
        float rstd = (float)(1.0 / sqrt(var + 1e-5));
        float a = rstd * gamma[n];
        g_bnA[n] = a;
        g_bnC[n] = beta[n] - (float)mean * a;
    }
}

// -------- K7: window sums with BN folded --------
__global__ void swin_kernel()
{
    int b = blockIdx.x;
    int j = blockIdx.y*128 + threadIdx.x;
    const float* base = g_T2 + (size_t)b*T2T*3200 + j;
    float tot = 0.f, v0 = 0.f, v1 = 0.f, v34 = 0.f, v35 = 0.f;
#pragma unroll
    for (int t = 0; t < T2T; t++) {
        float v = base[(size_t)t*3200];
        tot += v;
        if (t == 0)  v0  = v;
        if (t == 1)  v1  = v;
        if (t == 34) v34 = v;
        if (t == 35) v35 = v;
    }
    int n = j >> 6;
    float a = g_bnA[n], c = 34.f * g_bnC[n];
    g_S[((size_t)b*3 + 0)*3200 + j] = a*(tot - v34 - v35) + c;
    g_S[((size_t)b*3 + 1)*3200 + j] = a*(tot - v0  - v35) + c;
    g_S[((size_t)b*3 + 2)*3200 + j] = a*(tot - v0  - v1 ) + c;
}

// -------- K8a: pooled split-K partials --------
__global__ void pooled_part_kernel(const float* __restrict__ w)
{
    extern __shared__ float psm[];
    float* sS = psm;                 // 32*385
    float* sw = psm + 32*385;        // 16*384

    int kp = blockIdx.x, og = blockIdx.y;
    int tid = threadIdx.x;

    for (int idx = tid; idx < 32*384; idx += 256) {
        int b = idx / 384, kk = idx % 384;
        sS[b*385 + kk] = g_S[(size_t)b*9600 + kp*384 + kk];
    }
    for (int idx = tid; idx < 16*384; idx += 256) {
        int o = idx / 384, kk = idx % 384;
        sw[idx] = w[(size_t)(og*16 + o)*9600 + kp*384 + kk];
    }
    __syncthreads();

    int ol = tid >> 4, bp = tid & 15;
    const float* wr = sw + ol*384;
    const float* s0 = sS + (2*bp)*385;
    const float* s1 = sS + (2*bp+1)*385;
    float a0 = 0.f, a1 = 0.f;
#pragma unroll 8
    for (int kk = 0; kk < 384; kk++) {
        float wv = wr[kk];
        a0 += wv * s0[kk];
        a1 += wv * s1[kk];
    }
    g_poolPart[kp][og*16 + ol][2*bp]   = a0;
    g_poolPart[kp][og*16 + ol][2*bp+1] = a1;
}

// -------- K8b: pooled finalize --------
__global__ void pooled_final_kernel(const float* __restrict__ cb)
{
    int idx = blockIdx.x*256 + threadIdx.x;
    if (idx >= 128*32) return;
    int o = idx >> 5, b = idx & 31;
    float s = 0.f;
#pragma unroll
    for (int kp = 0; kp < 25; kp++)
        s += g_poolPart[kp][o][b];
    g_pooled[b*128 + o] = s * (1.f/34.f) + cb[o];
}

// -------- K9: fc --------
__global__ void fc_kernel(const float* __restrict__ f1w,
                          const float* __restrict__ f1b,
                          float* __restrict__ out)
{
    int q  = blockIdx.x*128 + threadIdx.x;
    int bg = blockIdx.y;
    __shared__ float sp[8*128];
    for (int i = threadIdx.x; i < 8*128; i += 128)
        sp[i] = g_pooled[bg*8*128 + i];
    __syncthreads();

    float acc[8];
#pragma unroll
    for (int b = 0; b < 8; b++) acc[b] = 0.f;
#pragma unroll 4
    for (int o = 0; o < 128; o++) {
        float wv = f1w[(size_t)o*3200 + q];
#pragma unroll
        for (int b = 0; b < 8; b++)
            acc[b] += sp[b*128 + o] * wv;
    }
    float bias = f1b[q];
#pragma unroll
    for (int b = 0; b < 8; b++)
        out[(size_t)(bg*8 + b)*3200 + q] = acc[b] + bias;
}

// ---------------- launch ----------------
extern "C" void kernel_launch(void* const* d_in, const int* in_sizes, int n_in,
                              void* d_out, int out_size)
{
    int iEI, iT1W1, iT1B1, iT1W2, iT1B2, iT1W3, iT1B3, iCW, iCB;
    int iT2W1, iT2B1, iT2W2, iT2B2, iT2W3, iT2B3, iGam, iBet, iC3W, iC3B, iF1W, iF1B;
    if (n_in > 1 && in_sizes[1] == BB*TW*2*EE) {
        iEI=1;  iT1W1=2;  iT1B1=3;  iT1W2=4;  iT1B2=5;  iT1W3=6;  iT1B3=7;
        iCW=8;  iCB=9;
        iT2W1=10; iT2B1=11; iT2W2=12; iT2B2=13; iT2W3=14; iT2B3=15;
        iGam=16; iBet=17; iC3W=18; iC3B=19; iF1W=20; iF1B=21;
    } else {
        iT1W1=1;  iT1B1=2;  iT1W2=3;  iT1B2=4;  iT1W3=5;  iT1B3=6;
        iCW=7;  iCB=8;
        iT2W1=9;  iT2B1=10; iT2W2=11; iT2B2=12; iT2W3=13; iT2B3=14;
        iGam=15; iBet=16; iC3W=17; iC3B=18; iF1W=19; iF1B=20; iEI=21;
    }

    const float* X    = (const float*)d_in[0];
    const int*   EI   = (const int*)  d_in[iEI];
    const float* t1w1 = (const float*)d_in[iT1W1];
    const float* t1b1 = (const float*)d_in[iT1B1];
    const float* t1w2 = (const float*)d_in[iT1W2];
    const float* t1b2 = (const float*)d_in[iT1B2];
    const float* t1w3 = (const float*)d_in[iT1W3];
    const float* t1b3 = (const float*)d_in[iT1B3];
    const float* chw  = (const float*)d_in[iCW];
    const float* chb  = (const float*)d_in[iCB];
    const float* t2w1 = (const float*)d_in[iT2W1];
    const float* t2b1 = (const float*)d_in[iT2B1];
    const float* t2w2 = (const float*)d_in[iT2W2];
    const float* t2b2 = (const float*)d_in[iT2B2];
    const float* t2w3 = (const float*)d_in[iT2W3];
    const float* t2b3 = (const float*)d_in[iT2B3];
    const float* gam  = (const float*)d_in[iGam];
    const float* bet  = (const float*)d_in[iBet];
    const float* c3w  = (const float*)d_in[iC3W];
    const float* c3b  = (const float*)d_in[iC3B];
    const float* f1w  = (const float*)d_in[iF1W];
    const float* f1b  = (const float*)d_in[iF1B];
    float* out = (float*)d_out;

    static const int PROP_SMEM  = (64 + 128) * LPAD * 4;             // 52,224 B
    static const int CHEB_SMEM  = 3*8192*4;                          // 98,304 B
    static const int T2_SMEM    = 3*10240*4;                         // 122,880 B
    static const int POOL_SMEM  = (32*385 + 16*384)*4;               // 73,856 B
    cudaFuncSetAttribute(prop_dense_kernel,
                         cudaFuncAttributeMaxDynamicSharedMemorySize, PROP_SMEM);
    cudaFuncSetAttribute(cheb_mma_kernel,
                         cudaFuncAttributeMaxDynamicSharedMemorySize, CHEB_SMEM);
    cudaFuncSetAttribute(tconv2_mma_kernel,
                         cudaFuncAttributeMaxDynamicSharedMemorySize, T2_SMEM);
    cudaFuncSetAttribute(pooled_part_kernel,
                         cudaFuncAttributeMaxDynamicSharedMemorySize, POOL_SMEM);

    tconv1_kernel<<<NSL, 128>>>(X, t1w1, t1b1, t1w2, t1b2, t1w3, t1b3);
    prep_w_kernel<<<(192*384 + 255)/256, 256>>>(chw, t2w1, t2w2, t2w3);
    prop_dense_kernel<<<NSL, 256, PROP_SMEM>>>(EI);
    cheb_mma_kernel<<<MCHEB/128, 256, CHEB_SMEM>>>(chb);
    tconv2_mma_kernel<<<MT2/128, 256, T2_SMEM>>>(t2b1, t2b2, t2b3);
    bn_part_kernel<<<dim3(NN, 4), 256>>>();
    bn_final_kernel<<<1, 64>>>(gam, bet);
    swin_kernel<<<dim3(BB, 25), 128>>>();
    pooled_part_kernel<<<dim3(25, 8), 256, POOL_SMEM>>>(c3w);
    pooled_final_kernel<<<16, 256>>>(c3b);
    fc_kernel<<<dim3(25, 4), 128>>>(f1w, f1b, out);
}